// round 6
// baseline (speedup 1.0000x reference)
#include <cuda_runtime.h>
#include <math.h>
#include <stdint.h>

#define H 2048
#define E 64
#define S 4096
#define B 2
#define SW 1024
#define NEGF (-3.4028234663852886e38f)   // -FLT_MAX == finfo(float32).min

#define OFF_SLID 33554432ull             // 2*4096*4096
#define OFF_W    67108864ull
#define OFF_I    67141632ull             // OFF_W + 8192*4

#define RSQRT_H 0.022097086912079608f    // 1/sqrt(2048)
#define GATE_BLOCKS 128

// scratch (no allocations allowed)
__device__ int4 g_qmeta[B * S];          // {flo, s1lo, v2lo, v2hi} per q

// ---------------------------------------------------------------------------
// packed fp32x2 FMA (sm_100+). Non-volatile: scheduler may pipeline around it.
// ---------------------------------------------------------------------------
__device__ __forceinline__ void ffma2(unsigned long long& d,
                                      unsigned long long a,
                                      unsigned long long b) {
    asm("fma.rn.f32x2 %0, %1, %2, %0;" : "+l"(d) : "l"(a), "l"(b));
}

// ---------------------------------------------------------------------------
// block-wide exclusive scans for the prep path (256 threads, 2 barriers each)
// ---------------------------------------------------------------------------
__device__ __forceinline__ int blk_excl_max(int agg, int t, int* sc) {
    int lane = t & 31, w = t >> 5;
    int inc = agg;
    #pragma unroll
    for (int o = 1; o < 32; o <<= 1) {
        int u = __shfl_up_sync(0xffffffffu, inc, o);
        if (lane >= o) inc = max(inc, u);
    }
    if (lane == 31) sc[w] = inc;
    __syncthreads();
    int wex = -0x7fffffff;
    for (int i = 0; i < w; i++) wex = max(wex, sc[i]);
    int lex = __shfl_up_sync(0xffffffffu, inc, 1);
    if (lane == 0) lex = -0x7fffffff;
    __syncthreads();
    return max(wex, lex);
}

__device__ __forceinline__ int blk_excl_min_bwd(int agg, int t, int* sc) {
    int lane = t & 31, w = t >> 5;
    int inc = agg;
    #pragma unroll
    for (int o = 1; o < 32; o <<= 1) {
        int u = __shfl_down_sync(0xffffffffu, inc, o);
        if (lane < 32 - o) inc = min(inc, u);
    }
    if (lane == 0) sc[w] = inc;
    __syncthreads();
    int wex = 0x7fffffff;
    for (int i = w + 1; i < 8; i++) wex = min(wex, sc[i]);
    int lex = __shfl_down_sync(0xffffffffu, inc, 1);
    if (lane == 31) lex = 0x7fffffff;
    __syncthreads();
    return min(wex, lex);
}

// ---------------------------------------------------------------------------
// K1: heterogeneous launch.
//   blocks [0,128): gate GEMM 64 rows x 64 experts, f32x2 FMA, reg prefetch
//   blocks [128,130): per-q interval metadata (prep) — hidden under gate
// ---------------------------------------------------------------------------
__global__ __launch_bounds__(256) void gate_prep_kernel(const float* __restrict__ x,
                                                        const float* __restrict__ scale,
                                                        const float* __restrict__ pw,
                                                        const int* __restrict__ packed,
                                                        const int* __restrict__ mm,
                                                        float* __restrict__ out) {
    if (blockIdx.x < GATE_BLOCKS) {
        // ================= GATE =================
        __shared__ __align__(16) float Xs2[32][132];  // k-major, duplicated pairs
        __shared__ __align__(16) float Ws[32][68];
        __shared__ float s_l[64][68];

        int bm  = blockIdx.x;
        int tid = threadIdx.x;
        int w   = tid >> 5, lane = tid & 31;
        int tr  = tid >> 4, tc = tid & 15;
        const float* xb = x + (size_t)bm * 64 * H;

        unsigned long long acc[4][2] = {};
        float ssacc[8] = {};
        float rx[8], rw[8], rscale;

        // prologue: tile 0
        rscale = scale[lane] * RSQRT_H;
        #pragma unroll
        for (int i = 0; i < 8; i++) {
            int row = w + 8 * i;
            rx[i] = xb[(size_t)row * H + lane];
            rw[i] = pw[row * H + lane];          // row == expert
        }

        for (int kt = 0; kt < 64; kt++) {
            if (kt) __syncthreads();             // prev compute done before overwrite
            #pragma unroll
            for (int i = 0; i < 8; i++) {
                int row = w + 8 * i;
                float vv = rx[i];
                ssacc[i] += vv * vv;
                *(float2*)&Xs2[lane][2 * row] = make_float2(vv, vv);
                Ws[lane][row] = rw[i] * rscale;
            }
            __syncthreads();
            if (kt < 63) {                       // prefetch next tile (overlaps compute)
                int k0 = (kt + 1) * 32 + lane;
                float ns = scale[k0];
                #pragma unroll
                for (int i = 0; i < 8; i++) {
                    int row = w + 8 * i;
                    rx[i] = xb[(size_t)row * H + k0];
                    rw[i] = pw[row * H + k0];
                }
                rscale = ns * RSQRT_H;
            }
            #pragma unroll
            for (int k = 0; k < 32; k++) {
                ulonglong2 xA = *(const ulonglong2*)&Xs2[k][8 * tr];
                ulonglong2 xB = *(const ulonglong2*)&Xs2[k][8 * tr + 4];
                ulonglong2 wA = *(const ulonglong2*)&Ws[k][4 * tc];
                ffma2(acc[0][0], xA.x, wA.x); ffma2(acc[0][1], xA.x, wA.y);
                ffma2(acc[1][0], xA.y, wA.x); ffma2(acc[1][1], xA.y, wA.y);
                ffma2(acc[2][0], xB.x, wA.x); ffma2(acc[2][1], xB.x, wA.y);
                ffma2(acc[3][0], xB.y, wA.x); ffma2(acc[3][1], xB.y, wA.y);
            }
        }

        #pragma unroll
        for (int i = 0; i < 4; i++) {
            #pragma unroll
            for (int pp = 0; pp < 2; pp++) {
                float lo, hi;
                asm("mov.b64 {%0,%1},%2;" : "=f"(lo), "=f"(hi) : "l"(acc[i][pp]));
                s_l[tr * 4 + i][tc * 4 + 2 * pp]     = lo;
                s_l[tr * 4 + i][tc * 4 + 2 * pp + 1] = hi;
            }
        }
        __syncthreads();

        // per-row top-4 + renormalized softmax (== softmax over top-4 logits)
        #pragma unroll
        for (int i = 0; i < 8; i++) {
            int rr = w + 8 * i;
            float s = ssacc[i];
            #pragma unroll
            for (int o = 16; o; o >>= 1) s += __shfl_xor_sync(0xffffffffu, s, o);
            float r = rsqrtf(s * (1.0f / H) + 1e-6f);
            float v0 = r * s_l[rr][lane];
            float v1 = r * s_l[rr][lane + 32];
            float vals[4]; int ids[4];
            #pragma unroll
            for (int t4 = 0; t4 < 4; t4++) {
                float cv; int ci;
                if (v1 > v0) { cv = v1; ci = lane + 32; }
                else         { cv = v0; ci = lane; }   // tie -> smaller index
                #pragma unroll
                for (int o = 16; o; o >>= 1) {
                    float ov = __shfl_xor_sync(0xffffffffu, cv, o);
                    int   oi = __shfl_xor_sync(0xffffffffu, ci, o);
                    if (ov > cv || (ov == cv && oi < ci)) { cv = ov; ci = oi; }
                }
                vals[t4] = cv; ids[t4] = ci;
                if (ci < 32) { if (lane == ci)      v0 = -3.4e38f; }
                else         { if (lane == ci - 32) v1 = -3.4e38f; }
            }
            if (lane == 0) {
                int row = bm * 64 + rr;
                float mmax = vals[0];
                float e0 = expf(vals[0] - mmax), e1 = expf(vals[1] - mmax);
                float e2 = expf(vals[2] - mmax), e3 = expf(vals[3] - mmax);
                float inv = 1.0f / (e0 + e1 + e2 + e3);
                float* ow = out + OFF_W + (size_t)row * 4;
                float* oi = out + OFF_I + (size_t)row * 4;
                ow[0] = e0 * inv; ow[1] = e1 * inv; ow[2] = e2 * inv; ow[3] = e3 * inv;
                oi[0] = (float)ids[0]; oi[1] = (float)ids[1];
                oi[2] = (float)ids[2]; oi[3] = (float)ids[3];
            }
        }
    } else {
        // ================= PREP =================
        __shared__ int sc[8];
        const int INF = 0x7fffffff;
        int b = blockIdx.x - GATE_BLOCKS;
        int t = threadIdx.x;
        int base = t * 16;
        const int* pk = packed + b * S;
        const int* m  = mm + b * S;

        int p[16]; bool v[16];
        #pragma unroll
        for (int c = 0; c < 4; c++) {
            int4 pp4 = ((const int4*)(pk + base))[c];
            int4 mm4 = ((const int4*)(m + base))[c];
            p[4*c+0] = pp4.x; p[4*c+1] = pp4.y; p[4*c+2] = pp4.z; p[4*c+3] = pp4.w;
            v[4*c+0] = (mm4.x == 1) | (mm4.x == 2);
            v[4*c+1] = (mm4.y == 1) | (mm4.y == 2);
            v[4*c+2] = (mm4.z == 1) | (mm4.z == 2);
            v[4*c+3] = (mm4.w == 1) | (mm4.w == 2);
        }
        int  pprev = (base > 0) ? pk[base - 1] : -123456;
        int  pnext = (base + 16 < S) ? pk[base + 16] : -123456;
        int  mprev = (base > 0) ? m[base - 1] : 0;
        int  mnext = (base + 16 < S) ? m[base + 16] : 0;
        bool vprev = (mprev == 1) | (mprev == 2);
        bool vnext = (mnext == 1) | (mnext == 2);

        // doc start: forward max
        int dloc[16];
        {
            int run = -1, pp = pprev;
            #pragma unroll
            for (int j = 0; j < 16; j++) {
                if (p[j] != pp) run = base + j;
                dloc[j] = run; pp = p[j];
            }
            int ex = blk_excl_max(run, t, sc);
            #pragma unroll
            for (int j = 0; j < 16; j++) if (ex > dloc[j]) dloc[j] = ex;
        }
        // vision run start: forward max
        int vloc[16];
        {
            int run = -1; bool pv = vprev;
            #pragma unroll
            for (int j = 0; j < 16; j++) {
                if (v[j] && !pv) run = base + j;
                vloc[j] = run; pv = v[j];
            }
            int ex = blk_excl_max(run, t, sc);
            #pragma unroll
            for (int j = 0; j < 16; j++) if (ex > vloc[j]) vloc[j] = ex;
        }
        // doc end: backward min
        int dend[16];
        {
            int run = INF, np = pnext;
            #pragma unroll
            for (int j = 15; j >= 0; j--) {
                if (p[j] != np) run = base + j;
                dend[j] = run; np = p[j];
            }
            int ex = blk_excl_min_bwd(run, t, sc);
            #pragma unroll
            for (int j = 0; j < 16; j++) if (ex < dend[j]) dend[j] = ex;
        }
        // vision run end: backward min
        int vend[16];
        {
            int run = INF; bool nv = vnext;
            #pragma unroll
            for (int j = 15; j >= 0; j--) {
                if (v[j] && !nv) run = base + j;
                vend[j] = run; nv = v[j];
            }
            int ex = blk_excl_min_bwd(run, t, sc);
            #pragma unroll
            for (int j = 0; j < 16; j++) if (ex < vend[j]) vend[j] = ex;
        }

        #pragma unroll
        for (int j = 0; j < 16; j++) {
            int q = base + j;
            int4 mt;
            if (p[j] <= 0) {
                mt.x = S; mt.y = S; mt.z = S; mt.w = -1;
            } else {
                int flo = dloc[j];
                mt.x = flo;
                int s1 = q - (SW - 1);
                mt.y = (s1 > flo) ? s1 : flo;
                if (v[j]) {
                    int vl = vloc[j]; if (flo > vl) vl = flo;
                    int vh = vend[j]; if (dend[j] < vh) vh = dend[j];
                    mt.z = vl; mt.w = vh;
                } else {
                    mt.z = S; mt.w = -1;
                }
            }
            g_qmeta[b * S + q] = mt;
        }
    }
}

// ---------------------------------------------------------------------------
// K2: mask writer. 2048 blocks x 4 q-rows, interval predicates, plain stores.
// ---------------------------------------------------------------------------
__global__ __launch_bounds__(256) void mask_kernel(float* __restrict__ out) {
    int mb = blockIdx.x;                    // 0 .. 2047
    int b  = mb >> 10;
    int q0 = (mb & 1023) << 2;
    int tid = threadIdx.x;

    float* fullb = out + (size_t)b * S * S;
    float* slidb = out + OFF_SLID + (size_t)b * S * S;

    #pragma unroll
    for (int qi = 0; qi < 4; qi++) {
        int q = q0 + qi;
        int4 mt = g_qmeta[b * S + q];       // {flo, s1lo, v2lo, v2hi}
        int flo = mt.x, slo = mt.y, vlo = mt.z;
        unsigned vspan = (unsigned)(mt.w - mt.z);
        float4* fo = (float4*)(fullb + (size_t)q * S);
        float4* so = (float4*)(slidb + (size_t)q * S);
        #pragma unroll
        for (int it = 0; it < 4; it++) {
            int k4 = tid + it * 256;
            int kv = k4 * 4;
            float4 f, sl;
            #pragma unroll
            for (int j = 0; j < 4; j++) {
                int k = kv + j;
                bool fb = (k >= flo) & (k <= q);
                bool sb = ((k >= slo) & (k <= q)) | ((unsigned)(k - vlo) <= vspan);
                (&f.x)[j]  = fb ? 0.0f : NEGF;
                (&sl.x)[j] = sb ? 0.0f : NEGF;
            }
            fo[k4] = f;
            so[k4] = sl;
        }
    }
}

// ---------------------------------------------------------------------------
extern "C" void kernel_launch(void* const* d_in, const int* in_sizes, int n_in,
                              void* d_out, int out_size) {
    const float* x      = (const float*)d_in[0];
    const int*   packed = (const int*)d_in[1];
    const int*   mm     = (const int*)d_in[2];
    const float* scale  = (const float*)d_in[3];
    const float* pw     = (const float*)d_in[4];
    float* out = (float*)d_out;

    gate_prep_kernel<<<GATE_BLOCKS + B, 256>>>(x, scale, pw, packed, mm, out);
    mask_kernel<<<2048, 256>>>(out);
}

// round 7
// speedup vs baseline: 1.3607x; 1.3607x over previous
#include <cuda_runtime.h>
#include <math.h>
#include <stdint.h>

#define H 2048
#define E 64
#define S 4096
#define B 2
#define SW 1024
#define NEGF (-3.4028234663852886e38f)   // -FLT_MAX == finfo(float32).min

#define OFF_SLID 33554432ull             // 2*4096*4096
#define OFF_W    67108864ull
#define OFF_I    67141632ull             // OFF_W + 8192*4

#define RSQRT_H 0.022097086912079608f    // 1/sqrt(2048)
#define KT 32                            // k-tile
#define PAD 68                           // row stride (floats) of k-major tiles
#define NKT (H / KT)                     // 64
#define TILE_F (KT * PAD)                // 2176 floats per W tile image
#define FOLD_BLOCKS 128

// scratch (no allocations allowed)
__device__ int4  g_qmeta[B * S];                       // {flo, s1lo, v2lo, v2hi}
__device__ __align__(16) float g_w2t[NKT * TILE_F];    // folded W, tile-image layout

// ---------------------------------------------------------------------------
// cp.async helpers
// ---------------------------------------------------------------------------
#define CP_ASYNC4(dst, src) \
    asm volatile("cp.async.ca.shared.global [%0], [%1], 4;" :: "r"(dst), "l"(src))
#define CP_ASYNC16(dst, src) \
    asm volatile("cp.async.cg.shared.global [%0], [%1], 16;" :: "r"(dst), "l"(src))
#define CP_COMMIT() asm volatile("cp.async.commit_group;")
#define CP_WAIT1()  asm volatile("cp.async.wait_group 1;")

// ---------------------------------------------------------------------------
// block-wide exclusive scans for prep (256 threads)
// ---------------------------------------------------------------------------
__device__ __forceinline__ int blk_excl_max(int agg, int t, int* sc) {
    int lane = t & 31, w = t >> 5;
    int inc = agg;
    #pragma unroll
    for (int o = 1; o < 32; o <<= 1) {
        int u = __shfl_up_sync(0xffffffffu, inc, o);
        if (lane >= o) inc = max(inc, u);
    }
    if (lane == 31) sc[w] = inc;
    __syncthreads();
    int wex = -0x7fffffff;
    for (int i = 0; i < w; i++) wex = max(wex, sc[i]);
    int lex = __shfl_up_sync(0xffffffffu, inc, 1);
    if (lane == 0) lex = -0x7fffffff;
    __syncthreads();
    return max(wex, lex);
}

__device__ __forceinline__ int blk_excl_min_bwd(int agg, int t, int* sc) {
    int lane = t & 31, w = t >> 5;
    int inc = agg;
    #pragma unroll
    for (int o = 1; o < 32; o <<= 1) {
        int u = __shfl_down_sync(0xffffffffu, inc, o);
        if (lane < 32 - o) inc = min(inc, u);
    }
    if (lane == 0) sc[w] = inc;
    __syncthreads();
    int wex = 0x7fffffff;
    for (int i = w + 1; i < 8; i++) wex = min(wex, sc[i]);
    int lex = __shfl_down_sync(0xffffffffu, inc, 1);
    if (lane == 31) lex = 0x7fffffff;
    __syncthreads();
    return min(wex, lex);
}

// ---------------------------------------------------------------------------
// K0: fold W into k-major tile images (+ prep blocks for mask metadata)
// ---------------------------------------------------------------------------
__global__ __launch_bounds__(256) void foldprep_kernel(const float* __restrict__ scale,
                                                       const float* __restrict__ pw,
                                                       const int* __restrict__ packed,
                                                       const int* __restrict__ mm) {
    if (blockIdx.x < FOLD_BLOCKS) {
        int i = blockIdx.x * 1024 + threadIdx.x * 4;     // over E*H = 131072
        float4 pw4 = *(const float4*)(pw + i);
        float4 sc4 = *(const float4*)(scale + (i & (H - 1)));
        int e  = i >> 11;
        int h  = i & (H - 1);
        int kt = h >> 5, k = h & 31;                     // k % 4 == 0
        float* dst = g_w2t + kt * TILE_F + k * PAD + e;
        dst[0 * PAD] = pw4.x * sc4.x * RSQRT_H;
        dst[1 * PAD] = pw4.y * sc4.y * RSQRT_H;
        dst[2 * PAD] = pw4.z * sc4.z * RSQRT_H;
        dst[3 * PAD] = pw4.w * sc4.w * RSQRT_H;
    } else {
        // ================= PREP =================
        __shared__ int sc[8];
        const int INF = 0x7fffffff;
        int b = blockIdx.x - FOLD_BLOCKS;
        int t = threadIdx.x;
        int base = t * 16;
        const int* pk = packed + b * S;
        const int* m  = mm + b * S;

        int p[16]; bool v[16];
        #pragma unroll
        for (int c = 0; c < 4; c++) {
            int4 pp4 = ((const int4*)(pk + base))[c];
            int4 mm4 = ((const int4*)(m + base))[c];
            p[4*c+0] = pp4.x; p[4*c+1] = pp4.y; p[4*c+2] = pp4.z; p[4*c+3] = pp4.w;
            v[4*c+0] = (mm4.x == 1) | (mm4.x == 2);
            v[4*c+1] = (mm4.y == 1) | (mm4.y == 2);
            v[4*c+2] = (mm4.z == 1) | (mm4.z == 2);
            v[4*c+3] = (mm4.w == 1) | (mm4.w == 2);
        }
        int  pprev = (base > 0) ? pk[base - 1] : -123456;
        int  pnext = (base + 16 < S) ? pk[base + 16] : -123456;
        int  mprev = (base > 0) ? m[base - 1] : 0;
        int  mnext = (base + 16 < S) ? m[base + 16] : 0;
        bool vprev = (mprev == 1) | (mprev == 2);
        bool vnext = (mnext == 1) | (mnext == 2);

        int dloc[16];
        {
            int run = -1, pp = pprev;
            #pragma unroll
            for (int j = 0; j < 16; j++) {
                if (p[j] != pp) run = base + j;
                dloc[j] = run; pp = p[j];
            }
            int ex = blk_excl_max(run, t, sc);
            #pragma unroll
            for (int j = 0; j < 16; j++) if (ex > dloc[j]) dloc[j] = ex;
        }
        int vloc[16];
        {
            int run = -1; bool pv = vprev;
            #pragma unroll
            for (int j = 0; j < 16; j++) {
                if (v[j] && !pv) run = base + j;
                vloc[j] = run; pv = v[j];
            }
            int ex = blk_excl_max(run, t, sc);
            #pragma unroll
            for (int j = 0; j < 16; j++) if (ex > vloc[j]) vloc[j] = ex;
        }
        int dend[16];
        {
            int run = INF, np = pnext;
            #pragma unroll
            for (int jj = 15; jj >= 0; jj--) {
                if (p[jj] != np) run = base + jj;
                dend[jj] = run; np = p[jj];
            }
            int ex = blk_excl_min_bwd(run, t, sc);
            #pragma unroll
            for (int j = 0; j < 16; j++) if (ex < dend[j]) dend[j] = ex;
        }
        int vend[16];
        {
            int run = INF; bool nv = vnext;
            #pragma unroll
            for (int jj = 15; jj >= 0; jj--) {
                if (v[jj] && !nv) run = base + jj;
                vend[jj] = run; nv = v[jj];
            }
            int ex = blk_excl_min_bwd(run, t, sc);
            #pragma unroll
            for (int j = 0; j < 16; j++) if (ex < vend[j]) vend[j] = ex;
        }

        #pragma unroll
        for (int j = 0; j < 16; j++) {
            int q = base + j;
            int4 mt;
            if (p[j] <= 0) {
                mt.x = S; mt.y = S; mt.z = S; mt.w = -1;
            } else {
                int flo = dloc[j];
                mt.x = flo;
                int s1 = q - (SW - 1);
                mt.y = (s1 > flo) ? s1 : flo;
                if (v[j]) {
                    int vl = vloc[j]; if (flo > vl) vl = flo;
                    int vh = vend[j]; if (dend[j] < vh) vh = dend[j];
                    mt.z = vl; mt.w = vh;
                } else {
                    mt.z = S; mt.w = -1;
                }
            }
            g_qmeta[b * S + q] = mt;
        }
    }
}

// ---------------------------------------------------------------------------
// K1: gate. 128 blocks x (64 rows x 64 experts), cp.async 2-stage pipeline,
// fp32 4x4 fragments, fused RMS (smem pass) + top-4 + renorm softmax.
// ---------------------------------------------------------------------------
__global__ __launch_bounds__(256) void gate_kernel(const float* __restrict__ x,
                                                   float* __restrict__ out) {
    __shared__ union USm {
        struct { float X[2][KT][PAD]; float W[2][KT][PAD]; } p;   // 34816 B
        float s_l[64][PAD];                                        // 17408 B
    } sm;
    __shared__ float s_ssq[64];

    int bm  = blockIdx.x;
    int tid = threadIdx.x;
    int w   = tid >> 5, lane = tid & 31;
    int tr  = tid >> 4, tc = tid & 15;
    const float* xb = x + (size_t)bm * 64 * H;

    uint32_t smb = (uint32_t)__cvta_generic_to_shared(&sm);
    const uint32_t XST = (uint32_t)(KT * PAD * 4);     // bytes per X stage
    uint32_t xbase = smb;
    uint32_t wbase = smb + 2 * XST;

    // per-thread cp.async addressing
    int lrow = tid >> 5;                               // 0..7 (+8i)
    int lk   = tid & 31;
    uint32_t xdst0 = xbase + (uint32_t)(lk * PAD + lrow) * 4u;
    const float* xsrc0 = xb + (size_t)lrow * H + lk;

    // prologue: tile 0 into stage 0
    {
        #pragma unroll
        for (int i = 0; i < 8; i++)
            CP_ASYNC4(xdst0 + (uint32_t)(8 * i) * 4u, xsrc0 + (size_t)(8 * i) * H);
        const float4* wsrc = (const float4*)(g_w2t);
        uint32_t wdst = wbase;
        CP_ASYNC16(wdst + (uint32_t)tid * 16u, wsrc + tid);
        CP_ASYNC16(wdst + (uint32_t)(tid + 256) * 16u, wsrc + tid + 256);
        if (tid < 32) CP_ASYNC16(wdst + (uint32_t)(tid + 512) * 16u, wsrc + tid + 512);
        CP_COMMIT();
    }

    float acc[4][4] = {};
    float ssq[8] = {};

    for (int kt = 0; kt < NKT; kt++) {
        int s = kt & 1;
        // issue tile kt+1 into the other stage
        if (kt + 1 < NKT) {
            int ns = (kt + 1) & 1;
            uint32_t xd = xdst0 + (uint32_t)ns * XST;
            const float* xs = xsrc0 + (size_t)(kt + 1) * KT;
            #pragma unroll
            for (int i = 0; i < 8; i++)
                CP_ASYNC4(xd + (uint32_t)(8 * i) * 4u, xs + (size_t)(8 * i) * H);
            const float4* wsrc = (const float4*)(g_w2t + (size_t)(kt + 1) * TILE_F);
            uint32_t wd = wbase + (uint32_t)ns * XST;
            CP_ASYNC16(wd + (uint32_t)tid * 16u, wsrc + tid);
            CP_ASYNC16(wd + (uint32_t)(tid + 256) * 16u, wsrc + tid + 256);
            if (tid < 32) CP_ASYNC16(wd + (uint32_t)(tid + 512) * 16u, wsrc + tid + 512);
        }
        CP_COMMIT();
        CP_WAIT1();           // tile kt resident
        __syncthreads();

        // compute on stage s
        #pragma unroll
        for (int k = 0; k < KT; k++) {
            float4 a = *(const float4*)&sm.p.X[s][k][4 * tr];
            float4 bfr = *(const float4*)&sm.p.W[s][k][4 * tc];
            float av[4] = { a.x, a.y, a.z, a.w };
            float bv[4] = { bfr.x, bfr.y, bfr.z, bfr.w };
            #pragma unroll
            for (int i = 0; i < 4; i++)
                #pragma unroll
                for (int j = 0; j < 4; j++)
                    acc[i][j] = fmaf(av[i], bv[j], acc[i][j]);
        }
        // rms sum-of-squares pass (lane = k, rows w+8i)
        #pragma unroll
        for (int i = 0; i < 8; i++) {
            float v = sm.p.X[s][lane][w + 8 * i];
            ssq[i] = fmaf(v, v, ssq[i]);
        }
        __syncthreads();       // stage s safe to refill next iteration
    }

    // epilogue: logits to smem (aliases stage memory — pipeline done)
    #pragma unroll
    for (int i = 0; i < 4; i++)
        #pragma unroll
        for (int j = 0; j < 4; j++)
            sm.s_l[4 * tr + i][4 * tc + j] = acc[i][j];
    if (tid < 64) { /* placeholder to keep s_ssq init simple */ }
    __syncthreads();

    // per-row top-4 + renormalized softmax (== softmax over top-4 logits)
    #pragma unroll
    for (int i = 0; i < 8; i++) {
        int rr = w + 8 * i;
        float s = ssq[i];
        #pragma unroll
        for (int o = 16; o; o >>= 1) s += __shfl_xor_sync(0xffffffffu, s, o);
        float r = rsqrtf(s * (1.0f / H) + 1e-6f);
        float v0 = r * sm.s_l[rr][lane];
        float v1 = r * sm.s_l[rr][lane + 32];
        float vals[4]; int ids[4];
        #pragma unroll
        for (int t4 = 0; t4 < 4; t4++) {
            float cv; int ci;
            if (v1 > v0) { cv = v1; ci = lane + 32; }
            else         { cv = v0; ci = lane; }   // tie -> smaller index
            #pragma unroll
            for (int o = 16; o; o >>= 1) {
                float ov = __shfl_xor_sync(0xffffffffu, cv, o);
                int   oi = __shfl_xor_sync(0xffffffffu, ci, o);
                if (ov > cv || (ov == cv && oi < ci)) { cv = ov; ci = oi; }
            }
            vals[t4] = cv; ids[t4] = ci;
            if (ci < 32) { if (lane == ci)      v0 = -3.4e38f; }
            else         { if (lane == ci - 32) v1 = -3.4e38f; }
        }
        if (lane == 0) {
            int row = bm * 64 + rr;
            float mmax = vals[0];
            float e0 = expf(vals[0] - mmax), e1 = expf(vals[1] - mmax);
            float e2 = expf(vals[2] - mmax), e3 = expf(vals[3] - mmax);
            float inv = 1.0f / (e0 + e1 + e2 + e3);
            float* ow = out + OFF_W + (size_t)row * 4;
            float* oi = out + OFF_I + (size_t)row * 4;
            ow[0] = e0 * inv; ow[1] = e1 * inv; ow[2] = e2 * inv; ow[3] = e3 * inv;
            oi[0] = (float)ids[0]; oi[1] = (float)ids[1];
            oi[2] = (float)ids[2]; oi[3] = (float)ids[3];
        }
    }
    (void)s_ssq;
}

// ---------------------------------------------------------------------------
// K2: mask writer. 2048 blocks x 4 q-rows, interval predicates, plain stores.
// ---------------------------------------------------------------------------
__global__ __launch_bounds__(256) void mask_kernel(float* __restrict__ out) {
    int mb = blockIdx.x;                    // 0 .. 2047
    int b  = mb >> 10;
    int q0 = (mb & 1023) << 2;
    int tid = threadIdx.x;

    float* fullb = out + (size_t)b * S * S;
    float* slidb = out + OFF_SLID + (size_t)b * S * S;

    #pragma unroll
    for (int qi = 0; qi < 4; qi++) {
        int q = q0 + qi;
        int4 mt = g_qmeta[b * S + q];       // {flo, s1lo, v2lo, v2hi}
        int flo = mt.x, slo = mt.y, vlo = mt.z;
        unsigned vspan = (unsigned)(mt.w - mt.z);
        float4* fo = (float4*)(fullb + (size_t)q * S);
        float4* so = (float4*)(slidb + (size_t)q * S);
        #pragma unroll
        for (int it = 0; it < 4; it++) {
            int k4 = tid + it * 256;
            int kv = k4 * 4;
            float4 f, sl;
            #pragma unroll
            for (int j = 0; j < 4; j++) {
                int k = kv + j;
                bool fb = (k >= flo) & (k <= q);
                bool sb = ((k >= slo) & (k <= q)) | ((unsigned)(k - vlo) <= vspan);
                (&f.x)[j]  = fb ? 0.0f : NEGF;
                (&sl.x)[j] = sb ? 0.0f : NEGF;
            }
            fo[k4] = f;
            so[k4] = sl;
        }
    }
}

// ---------------------------------------------------------------------------
extern "C" void kernel_launch(void* const* d_in, const int* in_sizes, int n_in,
                              void* d_out, int out_size) {
    const float* x      = (const float*)d_in[0];
    const int*   packed = (const int*)d_in[1];
    const int*   mm     = (const int*)d_in[2];
    const float* scale  = (const float*)d_in[3];
    const float* pw     = (const float*)d_in[4];
    float* out = (float*)d_out;

    foldprep_kernel<<<FOLD_BLOCKS + B, 256>>>(scale, pw, packed, mm);
    gate_kernel<<<128, 256>>>(x, out);
    mask_kernel<<<2048, 256>>>(out);
}